// round 14
// baseline (speedup 1.0000x reference)
#include <cuda_runtime.h>
#include <cuda_bf16.h>
#include <cstdint>

// Problem constants
#define NN 50000
#define EE 500000
#define RR 8
#define HD 128
#define NG 64
#define NC 16
#define NTILES ((NN + 127) / 128)   // 391
#define NBLK ((NN + 255) / 256)     // 196
// chunk split: tiles [0,196) / [196,391); node boundary 196*128 = 25088
#define CH_TILES0 196
#define CH_TILES1 (NTILES - CH_TILES0)
#define CH_NODES0 (CH_TILES0 * 128)

// ---------------- scratch (device globals; no allocs allowed) ----------------
__device__ __align__(16) __nv_bfloat16 g_xwb0[(size_t)NN * 1024];  // layer-1 messages
__device__ __align__(16) __nv_bfloat16 g_xwb1[(size_t)NN * 1024];  // layer-2 messages
__device__ float g_hacc0[(size_t)NN * HD];     // layer-1 accumulator
__device__ float g_hacc1[(size_t)NN * HD];     // layer-2 accumulator
__device__ __align__(16) __nv_bfloat16 g_wh[9 * 128 * 128];  // weight hi, [ct][n][k]
__device__ __align__(16) __nv_bfloat16 g_wl[9 * 128 * 128];  // weight lo, [ct][n][k]
__device__ int   g_cnt[NN * RR];               // per (dst, rel) counts
__device__ int   g_ncnt[NN];                   // per dst counts
__device__ int   g_off[NN];                    // CSR offsets
__device__ int   g_cur[NN];                    // scatter cursors
__device__ int   g_bsum[256];                  // block sums for scan
__device__ int   g_bbase[256];                 // scanned block bases
__device__ int2  g_edges[EE];                  // dst-sorted: {src*8+rel, coef bits}
__device__ float g_pool[NG * HD];
__device__ float g_pcnt[NG];

// ---------------- helpers ----------------
__device__ __forceinline__ uint32_t smem_to_u32(const void* p) {
    uint32_t a;
    asm("{ .reg .u64 t; cvta.to.shared.u64 t, %1; cvt.u32.u64 %0, t; }" : "=r"(a) : "l"(p));
    return a;
}
__device__ __forceinline__ uint32_t pack_bf2(__nv_bfloat16 a, __nv_bfloat16 b) {
    __nv_bfloat162 t = __halves2bfloat162(a, b);
    return *reinterpret_cast<uint32_t*>(&t);
}
__device__ __forceinline__ void split_bf(float v, __nv_bfloat16& h, __nv_bfloat16& l) {
    h = __float2bfloat16(v);
    l = __float2bfloat16(v - __bfloat162float(h));
}
__device__ __forceinline__ void cp16(uint32_t dst, const void* src) {
    asm volatile("cp.async.cg.shared.global [%0], [%1], 16;" :: "r"(dst), "l"(src));
}
#define CP_COMMIT() asm volatile("cp.async.commit_group;" ::: "memory")
#define CP_WAIT(n)  asm volatile("cp.async.wait_group %0;" :: "n"(n) : "memory")

__device__ __forceinline__ void ldsm_x4(uint32_t addr, uint32_t& r0, uint32_t& r1,
                                        uint32_t& r2, uint32_t& r3) {
    asm volatile("ldmatrix.sync.aligned.m8n8.x4.shared.b16 {%0,%1,%2,%3}, [%4];"
                 : "=r"(r0), "=r"(r1), "=r"(r2), "=r"(r3) : "r"(addr));
}
__device__ __forceinline__ void mma16816(float* c, const uint32_t* a, const uint32_t* b) {
    asm volatile("mma.sync.aligned.m16n8k16.row.col.f32.bf16.bf16.f32 "
                 "{%0,%1,%2,%3}, {%4,%5,%6,%7}, {%8,%9}, {%0,%1,%2,%3};"
                 : "+f"(c[0]), "+f"(c[1]), "+f"(c[2]), "+f"(c[3])
                 : "r"(a[0]), "r"(a[1]), "r"(a[2]), "r"(a[3]), "r"(b[0]), "r"(b[1]));
}

// smem layout (bytes): padded rows 136 bf16 = 272 B; tile = 128*272 = 34816
#define ROWB 272
#define TILEB 34816
#define SM_A_HI 0
#define SM_A_LO 34816
#define SM_BH0  69632
#define SM_BH1  104448
#define SM_BL   139264
#define SMEM_TOTAL 174080

// ---------------- structure kernels ----------------
__global__ void zero_kernel() {
    int i = blockIdx.x * blockDim.x + threadIdx.x;
    if (i < NN * RR) g_cnt[i] = 0;
    if (i < NN) g_ncnt[i] = 0;
    if (i < NG * HD) g_pool[i] = 0.0f;
    if (i < NG) g_pcnt[i] = 0.0f;
}
__global__ void count_kernel(const int* __restrict__ dst, const int* __restrict__ rel,
                             const int* __restrict__ batch) {
    int e = blockIdx.x * blockDim.x + threadIdx.x;
    if (e < EE) {
        int d = dst[e];
        atomicAdd(&g_cnt[d * RR + rel[e]], 1);
        atomicAdd(&g_ncnt[d], 1);
    }
    if (e < NN)
        asm volatile("red.global.add.f32 [%0], %1;" :: "l"(&g_pcnt[batch[e]]), "f"(1.0f) : "memory");
}
__global__ void scan_bsum_kernel() {
    __shared__ int s[256];
    int i = blockIdx.x * 256 + threadIdx.x;
    int t = threadIdx.x;
    s[t] = (i < NN) ? g_ncnt[i] : 0;
    __syncthreads();
    for (int st = 128; st > 0; st >>= 1) {
        if (t < st) s[t] += s[t + st];
        __syncthreads();
    }
    if (t == 0) g_bsum[blockIdx.x] = s[0];
}
__global__ void scan_base_kernel() {
    __shared__ int s[256];
    int t = threadIdx.x;
    int v = (t < NBLK) ? g_bsum[t] : 0;
    s[t] = v;
    __syncthreads();
    for (int st = 1; st < 256; st <<= 1) {
        int add = (t >= st) ? s[t - st] : 0;
        __syncthreads();
        s[t] += add;
        __syncthreads();
    }
    if (t < NBLK) g_bbase[t] = s[t] - v;
}
__global__ void scan_final_kernel() {
    __shared__ int s[256];
    int i = blockIdx.x * 256 + threadIdx.x;
    int t = threadIdx.x;
    int v = (i < NN) ? g_ncnt[i] : 0;
    s[t] = v;
    __syncthreads();
    for (int st = 1; st < 256; st <<= 1) {
        int add = (t >= st) ? s[t - st] : 0;
        __syncthreads();
        s[t] += add;
        __syncthreads();
    }
    if (i < NN) {
        int off = g_bbase[blockIdx.x] + s[t] - v;
        g_off[i] = off;
        g_cur[i] = off;
    }
}
__global__ void scatter_kernel(const int* __restrict__ src, const int* __restrict__ dst,
                               const int* __restrict__ rel) {
    int e = blockIdx.x * blockDim.x + threadIdx.x;
    if (e >= EE) return;
    int d = dst[e], r = rel[e];
    int c = g_cnt[d * RR + r];
    float coef = 1.0f / (float)max(c, 1);
    int pos = atomicAdd(&g_cur[d], 1);
    g_edges[pos] = make_int2(src[e] * 8 + r, __float_as_int(coef));
}

// pack weights: split fp32 -> bf16 hi/lo, layout [ct][n][k]
__global__ void pack_w_kernel(const float* __restrict__ W, const float* __restrict__ root) {
    int i = blockIdx.x * blockDim.x + threadIdx.x;
    if (i >= 9 * 128 * 128) return;
    int ct = i >> 14;
    int rem = i & 16383;
    int n = rem >> 7;
    int k = rem & 127;
    float v = (ct < 8) ? W[((size_t)ct * 128 + k) * 128 + n] : root[(size_t)k * 128 + n];
    __nv_bfloat16 h, l;
    split_bf(v, h, l);
    g_wh[i] = h;
    g_wl[i] = l;
}

// ---------------- mma.sync GEMM (R7/R11 config): A[M,128] @ Wcat[128,1152] ----------------
// mt0: tile offset for chunked launches. msg: output message buffer (bf16).
__global__ __launch_bounds__(256, 1)
void gemm_mma_kernel(const float* __restrict__ x_in, const float* __restrict__ bias, int layer,
                     int mt0, __nv_bfloat16* __restrict__ msg) {
    extern __shared__ char smem[];
    const float* __restrict__ A = (layer == 0) ? x_in : g_hacc0;
    float* __restrict__ outroot = (layer == 0) ? g_hacc0 : g_hacc1;
    const bool relu = (layer != 0);

    const int tid = threadIdx.x;
    const int wid = tid >> 5, lane = tid & 31;
    const int warp_m = wid >> 2;
    const int warp_n = wid & 3;
    const int mt = blockIdx.x + mt0;
    const uint32_t su = smem_to_u32(smem);

    const uint32_t a_lane = (uint32_t)(warp_m * 64 + ((lane >> 3) & 1) * 8 + (lane & 7)) * ROWB
                          + (uint32_t)(lane >> 4) * 16;
    const uint32_t b_lane = (uint32_t)(warp_n * 32 + ((lane >> 4) & 1) * 8 + (lane & 7)) * ROWB
                          + (uint32_t)((lane >> 3) & 1) * 16;

    float2 bv[4];
    #pragma unroll
    for (int ni = 0; ni < 4; ni++)
        bv[ni] = *(const float2*)(bias + warp_n * 32 + ni * 8 + (lane & 3) * 2);

    // ---- load + split A tile (once per block) ----
    {
        int row = tid >> 1;
        int kh = (tid & 1) * 64;
        int m = mt * 128 + row;
        const float* ap = A + (size_t)m * 128 + kh;
        char* dh = smem + SM_A_HI + row * ROWB + kh * 2;
        char* dl = smem + SM_A_LO + row * ROWB + kh * 2;
        #pragma unroll
        for (int j = 0; j < 16; j++) {
            float4 v = make_float4(0.f, 0.f, 0.f, 0.f);
            if (m < NN) v = *(const float4*)(ap + 4 * j);
            if (relu) {
                v.x = fmaxf(v.x, 0.f); v.y = fmaxf(v.y, 0.f);
                v.z = fmaxf(v.z, 0.f); v.w = fmaxf(v.w, 0.f);
            }
            __nv_bfloat16 h0, l0, h1, l1, h2, l2, h3, l3;
            split_bf(v.x, h0, l0); split_bf(v.y, h1, l1);
            split_bf(v.z, h2, l2); split_bf(v.w, h3, l3);
            *(uint32_t*)(dh + 8 * j)     = pack_bf2(h0, h1);
            *(uint32_t*)(dh + 8 * j + 4) = pack_bf2(h2, h3);
            *(uint32_t*)(dl + 8 * j)     = pack_bf2(l0, l1);
            *(uint32_t*)(dl + 8 * j + 4) = pack_bf2(l2, l3);
        }
    }

    #define PF_TILE(gsrc, ct_, smoff) do {                                            \
        int n_ = tid >> 1, half_ = tid & 1;                                           \
        const char* s_ = (const char*)((gsrc) + (size_t)(ct_) * 16384 + n_ * 128 + half_ * 64); \
        uint32_t d_ = su + (smoff) + n_ * ROWB + half_ * 128;                         \
        _Pragma("unroll")                                                             \
        for (int j_ = 0; j_ < 8; j_++) cp16(d_ + 16 * j_, s_ + 16 * j_);              \
    } while (0)

    PF_TILE(g_wh, 0, SM_BH0);
    CP_COMMIT();

    const uint32_t as_h = su + SM_A_HI + a_lane;
    const uint32_t as_l = su + SM_A_LO + a_lane;
    const uint32_t bs_l = su + SM_BL + b_lane;

    #define LOAD_A4(dst, base, koff) do {                                             \
        _Pragma("unroll")                                                             \
        for (int mi = 0; mi < 4; mi++)                                                \
            ldsm_x4((base) + mi * (16 * ROWB) + (koff),                               \
                    dst[mi][0], dst[mi][1], dst[mi][2], dst[mi][3]);                  \
    } while (0)
    #define LOAD_B4(dst, base, koff) do {                                             \
        _Pragma("unroll")                                                             \
        for (int p = 0; p < 2; p++) {                                                 \
            uint32_t r0, r1, r2, r3;                                                  \
            ldsm_x4((base) + p * (16 * ROWB) + (koff), r0, r1, r2, r3);               \
            dst[2 * p][0] = r0; dst[2 * p][1] = r1;                                   \
            dst[2 * p + 1][0] = r2; dst[2 * p + 1][1] = r3;                           \
        }                                                                             \
    } while (0)

    for (int ct = 0; ct < 9; ct++) {
        const uint32_t bs_h = su + ((ct & 1) ? SM_BH1 : SM_BH0) + b_lane;

        if (ct < 8) {
            PF_TILE(g_wh, ct + 1, (ct & 1) ? SM_BH0 : SM_BH1);
            if (ct == 7) PF_TILE(g_wl, 8, SM_BL);
            CP_COMMIT();
            CP_WAIT(1);
        } else {
            CP_WAIT(0);
        }
        __syncthreads();

        float c[4][4][4];
        #pragma unroll
        for (int mi = 0; mi < 4; mi++)
            #pragma unroll
            for (int ni = 0; ni < 4; ni++)
                #pragma unroll
                for (int q = 0; q < 4; q++) c[mi][ni][q] = 0.0f;

        if (ct < 8) {
            uint32_t ah[2][4][4], bh[2][4][2];
            LOAD_A4(ah[0], as_h, 0u);
            LOAD_B4(bh[0], bs_h, 0u);
            #pragma unroll
            for (int k0 = 0; k0 < 8; k0++) {
                const int cur = k0 & 1;
                if (k0 < 7) {
                    LOAD_A4(ah[cur ^ 1], as_h, (uint32_t)(k0 + 1) * 32u);
                    LOAD_B4(bh[cur ^ 1], bs_h, (uint32_t)(k0 + 1) * 32u);
                }
                #pragma unroll
                for (int mi = 0; mi < 4; mi++)
                    #pragma unroll
                    for (int ni = 0; ni < 4; ni++)
                        mma16816(c[mi][ni], ah[cur][mi], bh[cur][ni]);
            }
            #pragma unroll
            for (int mi = 0; mi < 4; mi++) {
                int row0 = mt * 128 + warp_m * 64 + mi * 16 + (lane >> 2);
                int row1 = row0 + 8;
                #pragma unroll
                for (int ni = 0; ni < 4; ni++) {
                    int col = warp_n * 32 + ni * 8 + (lane & 3) * 2;
                    if (row0 < NN)
                        *(uint32_t*)(msg + (size_t)row0 * 1024 + ct * 128 + col) =
                            pack_bf2(__float2bfloat16(c[mi][ni][0]), __float2bfloat16(c[mi][ni][1]));
                    if (row1 < NN)
                        *(uint32_t*)(msg + (size_t)row1 * 1024 + ct * 128 + col) =
                            pack_bf2(__float2bfloat16(c[mi][ni][2]), __float2bfloat16(c[mi][ni][3]));
                }
            }
        } else {
            uint32_t ah[2][4][4], al[2][4][4], bh[2][4][2], bl[2][4][2];
            LOAD_A4(ah[0], as_h, 0u); LOAD_A4(al[0], as_l, 0u);
            LOAD_B4(bh[0], bs_h, 0u); LOAD_B4(bl[0], bs_l, 0u);
            #pragma unroll
            for (int k0 = 0; k0 < 8; k0++) {
                const int cur = k0 & 1;
                if (k0 < 7) {
                    const uint32_t koff = (uint32_t)(k0 + 1) * 32u;
                    LOAD_A4(ah[cur ^ 1], as_h, koff); LOAD_A4(al[cur ^ 1], as_l, koff);
                    LOAD_B4(bh[cur ^ 1], bs_h, koff); LOAD_B4(bl[cur ^ 1], bs_l, koff);
                }
                #pragma unroll
                for (int mi = 0; mi < 4; mi++)
                    #pragma unroll
                    for (int ni = 0; ni < 4; ni++) {
                        mma16816(c[mi][ni], ah[cur][mi], bh[cur][ni]);
                        mma16816(c[mi][ni], ah[cur][mi], bl[cur][ni]);
                        mma16816(c[mi][ni], al[cur][mi], bh[cur][ni]);
                    }
            }
            #pragma unroll
            for (int mi = 0; mi < 4; mi++) {
                int row0 = mt * 128 + warp_m * 64 + mi * 16 + (lane >> 2);
                int row1 = row0 + 8;
                #pragma unroll
                for (int ni = 0; ni < 4; ni++) {
                    int col = warp_n * 32 + ni * 8 + (lane & 3) * 2;
                    if (row0 < NN)
                        *(float2*)(outroot + (size_t)row0 * 128 + col) =
                            make_float2(c[mi][ni][0] + bv[ni].x, c[mi][ni][1] + bv[ni].y);
                    if (row1 < NN)
                        *(float2*)(outroot + (size_t)row1 * 128 + col) =
                            make_float2(c[mi][ni][2] + bv[ni].x, c[mi][ni][3] + bv[ni].y);
                }
            }
        }

        __syncthreads();
    }
    #undef LOAD_A4
    #undef LOAD_B4
    #undef PF_TILE
}

// ---------------- aggregation: one warp per dst node, no atomics, MLP 2 ----------------
// node range [node0, node0+nnodes); msg: input message buffer.
__global__ void agg_kernel(const int* __restrict__ batch, int layer, int node0, int nnodes,
                           const __nv_bfloat16* __restrict__ msg) {
    int idx = (blockIdx.x * blockDim.x + threadIdx.x) >> 5;
    int lane = threadIdx.x & 31;
    if (idx >= nnodes) return;
    int node = node0 + idx;
    int off = g_off[node];
    int n = g_ncnt[node];

    float ax = 0.f, ay = 0.f, az = 0.f, aw = 0.f;
    int i = 0;
    for (; i + 1 < n; i += 2) {
        int2 e0 = __ldg(&g_edges[off + i]);
        int2 e1 = __ldg(&g_edges[off + i + 1]);
        const uint2 r0 = *(const uint2*)(msg + (size_t)e0.x * 128 + lane * 4);
        const uint2 r1 = *(const uint2*)(msg + (size_t)e1.x * 128 + lane * 4);
        float c0 = __int_as_float(e0.y);
        float c1 = __int_as_float(e1.y);
        float2 p0 = __bfloat1622float2(*reinterpret_cast<const __nv_bfloat162*>(&r0.x));
        float2 p1 = __bfloat1622float2(*reinterpret_cast<const __nv_bfloat162*>(&r0.y));
        float2 q0 = __bfloat1622float2(*reinterpret_cast<const __nv_bfloat162*>(&r1.x));
        float2 q1 = __bfloat1622float2(*reinterpret_cast<const __nv_bfloat162*>(&r1.y));
        ax = fmaf(p0.x, c0, ax); ay = fmaf(p0.y, c0, ay);
        az = fmaf(p1.x, c0, az); aw = fmaf(p1.y, c0, aw);
        ax = fmaf(q0.x, c1, ax); ay = fmaf(q0.y, c1, ay);
        az = fmaf(q1.x, c1, az); aw = fmaf(q1.y, c1, aw);
    }
    if (i < n) {
        int2 e0 = __ldg(&g_edges[off + i]);
        const uint2 r0 = *(const uint2*)(msg + (size_t)e0.x * 128 + lane * 4);
        float c0 = __int_as_float(e0.y);
        float2 p0 = __bfloat1622float2(*reinterpret_cast<const __nv_bfloat162*>(&r0.x));
        float2 p1 = __bfloat1622float2(*reinterpret_cast<const __nv_bfloat162*>(&r0.y));
        ax = fmaf(p0.x, c0, ax); ay = fmaf(p0.y, c0, ay);
        az = fmaf(p1.x, c0, az); aw = fmaf(p1.y, c0, aw);
    }

    if (layer == 0) {
        float4 h = *(float4*)(g_hacc0 + (size_t)node * 128 + lane * 4);
        h.x += ax; h.y += ay; h.z += az; h.w += aw;
        *(float4*)(g_hacc0 + (size_t)node * 128 + lane * 4) = h;
    } else {
        float4 h = *(float4*)(g_hacc1 + (size_t)node * 128 + lane * 4);
        h.x = fmaxf(h.x + ax, 0.f);
        h.y = fmaxf(h.y + ay, 0.f);
        h.z = fmaxf(h.z + az, 0.f);
        h.w = fmaxf(h.w + aw, 0.f);
        int g = __ldg(&batch[node]);
        float* o = g_pool + (size_t)g * HD + lane * 4;
        asm volatile("red.global.add.v4.f32 [%0], {%1, %2, %3, %4};"
                     :: "l"(o), "f"(h.x), "f"(h.y), "f"(h.z), "f"(h.w) : "memory");
    }
}

// ---------------- head ----------------
__global__ void final_kernel(const float* __restrict__ linW, const float* __restrict__ linb,
                             float* __restrict__ out) {
    int g = blockIdx.x;
    int tid = threadIdx.x;  // 128
    __shared__ float p[HD];
    float cnt = fmaxf(g_pcnt[g], 1.0f);
    p[tid] = g_pool[g * HD + tid] / cnt;
    __syncthreads();
    if (tid < NC) {
        float s = linb[tid];
        #pragma unroll 8
        for (int h = 0; h < HD; h++) s = fmaf(p[h], linW[h * NC + tid], s);
        out[g * NC + tid] = s;
    }
}

// ---------------- launch: fork-join overlap + chunked layer-boundary pipeline ----------------
extern "C" void kernel_launch(void* const* d_in, const int* in_sizes, int n_in,
                              void* d_out, int out_size) {
    const float* x     = (const float*)d_in[0];
    const int*   eidx  = (const int*)d_in[1];
    const int*   etype = (const int*)d_in[2];
    const int*   batch = (const int*)d_in[3];
    const float* W1    = (const float*)d_in[4];
    const float* root1 = (const float*)d_in[5];
    const float* b1    = (const float*)d_in[6];
    const float* W2    = (const float*)d_in[7];
    const float* root2 = (const float*)d_in[8];
    const float* b2    = (const float*)d_in[9];
    const float* linW  = (const float*)d_in[10];
    const float* linb  = (const float*)d_in[11];
    float* out = (float*)d_out;

    const int* src = eidx;
    const int* dst = eidx + EE;

    static bool init_done = false;
    static cudaStream_t s2;
    static cudaEvent_t ev_fork, ev_struct, ev_g0, ev_a0a, ev_a0b, ev_g1;
    static __nv_bfloat16 *p_xwb0, *p_xwb1;
    if (!init_done) {
        cudaFuncSetAttribute(gemm_mma_kernel, cudaFuncAttributeMaxDynamicSharedMemorySize, SMEM_TOTAL);
        cudaStreamCreateWithFlags(&s2, cudaStreamNonBlocking);
        cudaEventCreateWithFlags(&ev_fork, cudaEventDisableTiming);
        cudaEventCreateWithFlags(&ev_struct, cudaEventDisableTiming);
        cudaEventCreateWithFlags(&ev_g0, cudaEventDisableTiming);
        cudaEventCreateWithFlags(&ev_a0a, cudaEventDisableTiming);
        cudaEventCreateWithFlags(&ev_a0b, cudaEventDisableTiming);
        cudaEventCreateWithFlags(&ev_g1, cudaEventDisableTiming);
        cudaGetSymbolAddress((void**)&p_xwb0, g_xwb0);
        cudaGetSymbolAddress((void**)&p_xwb1, g_xwb1);
        init_done = true;
    }

    int pack_blocks = (9 * 128 * 128 + 255) / 256;
    const int aggA_blocks = (CH_NODES0 * 32 + 255) / 256;
    const int aggB_blocks = ((NN - CH_NODES0) * 32 + 255) / 256;
    const int agg_blocks  = (NN * 32 + 255) / 256;

    // fork stream B off the main (capture) stream
    cudaEventRecord(ev_fork, 0);
    cudaStreamWaitEvent(s2, ev_fork, 0);

    // ---- stream B: structure phase (independent of weights/GEMM) ----
    zero_kernel<<<(NN * RR + 255) / 256, 256, 0, s2>>>();
    count_kernel<<<(EE + 255) / 256, 256, 0, s2>>>(dst, etype, batch);
    scan_bsum_kernel<<<NBLK, 256, 0, s2>>>();
    scan_base_kernel<<<1, 256, 0, s2>>>();
    scan_final_kernel<<<NBLK, 256, 0, s2>>>();
    scatter_kernel<<<(EE + 255) / 256, 256, 0, s2>>>(src, dst, etype);
    cudaEventRecord(ev_struct, s2);

    // ---- main: pack W1 + full layer-1 GEMM (messages -> buf0) ----
    pack_w_kernel<<<pack_blocks, 256>>>(W1, root1);
    gemm_mma_kernel<<<NTILES, 256, SMEM_TOTAL>>>(x, b1, 0, 0, p_xwb0);
    cudaEventRecord(ev_g0, 0);

    // stream B: pack W2 once gemm(0) stops reading the weight buffers
    cudaStreamWaitEvent(s2, ev_g0, 0);
    pack_w_kernel<<<pack_blocks, 256, 0, s2>>>(W2, root2);

    // ---- main: agg(0) in two node chunks (reads buf0, writes hacc0) ----
    cudaStreamWaitEvent(0, ev_struct, 0);
    agg_kernel<<<aggA_blocks, 256>>>(batch, 0, 0, CH_NODES0, p_xwb0);
    cudaEventRecord(ev_a0a, 0);
    agg_kernel<<<aggB_blocks, 256>>>(batch, 0, CH_NODES0, NN - CH_NODES0, p_xwb0);
    cudaEventRecord(ev_a0b, 0);

    // ---- stream B: layer-2 GEMM in matching tile chunks (writes buf1) ----
    // chunk A overlaps with agg(0) chunk B on the main stream
    cudaStreamWaitEvent(s2, ev_a0a, 0);
    gemm_mma_kernel<<<CH_TILES0, 256, SMEM_TOTAL, s2>>>(x, b2, 1, 0, p_xwb1);
    cudaStreamWaitEvent(s2, ev_a0b, 0);
    gemm_mma_kernel<<<CH_TILES1, 256, SMEM_TOTAL, s2>>>(x, b2, 1, CH_TILES0, p_xwb1);
    cudaEventRecord(ev_g1, s2);

    // ---- main: agg(1) (needs all of buf1) + head ----
    cudaStreamWaitEvent(0, ev_g1, 0);
    agg_kernel<<<agg_blocks, 256>>>(batch, 1, 0, NN, p_xwb1);
    final_kernel<<<NG, 128>>>(linW, linb, out);
}

// round 15
// speedup vs baseline: 1.1117x; 1.1117x over previous
#include <cuda_runtime.h>
#include <cuda_bf16.h>
#include <cstdint>

// Problem constants
#define NN 50000
#define EE 500000
#define RR 8
#define HD 128
#define NG 64
#define NC 16
#define NTILES ((NN + 127) / 128)   // 391
#define NBLK ((NN + 255) / 256)     // 196
// wave-aligned chunk split: gemm1 chunk A = exactly 1 wave (148 CTAs @ 1 CTA/SM)
#define CH_TILES0 148
#define CH_TILES1 (NTILES - CH_TILES0)   // 243
#define CH_NODES0 (CH_TILES0 * 128)      // 18944

// ---------------- scratch (device globals; no allocs allowed) ----------------
__device__ __align__(16) __nv_bfloat16 g_xwb0[(size_t)NN * 1024];  // layer-1 messages
__device__ __align__(16) __nv_bfloat16 g_xwb1[(size_t)NN * 1024];  // layer-2 messages
__device__ float g_hacc0[(size_t)NN * HD];     // layer-1 accumulator
__device__ float g_hacc1[(size_t)NN * HD];     // layer-2 accumulator
__device__ __align__(16) __nv_bfloat16 g_wh[9 * 128 * 128];  // weight hi, [ct][n][k]
__device__ __align__(16) __nv_bfloat16 g_wl[9 * 128 * 128];  // weight lo, [ct][n][k]
__device__ int   g_cnt[NN * RR];               // per (dst, rel) counts
__device__ int   g_ncnt[NN];                   // per dst counts
__device__ int   g_off[NN];                    // CSR offsets
__device__ int   g_cur[NN];                    // scatter cursors
__device__ int   g_bsum[256];                  // block sums for scan
__device__ int   g_bbase[256];                 // scanned block bases
__device__ int2  g_edges[EE];                  // dst-sorted: {src*8+rel, coef bits}
__device__ float g_pool[NG * HD];
__device__ float g_pcnt[NG];

// ---------------- helpers ----------------
__device__ __forceinline__ uint32_t smem_to_u32(const void* p) {
    uint32_t a;
    asm("{ .reg .u64 t; cvta.to.shared.u64 t, %1; cvt.u32.u64 %0, t; }" : "=r"(a) : "l"(p));
    return a;
}
__device__ __forceinline__ uint32_t pack_bf2(__nv_bfloat16 a, __nv_bfloat16 b) {
    __nv_bfloat162 t = __halves2bfloat162(a, b);
    return *reinterpret_cast<uint32_t*>(&t);
}
__device__ __forceinline__ void split_bf(float v, __nv_bfloat16& h, __nv_bfloat16& l) {
    h = __float2bfloat16(v);
    l = __float2bfloat16(v - __bfloat162float(h));
}
__device__ __forceinline__ void cp16(uint32_t dst, const void* src) {
    asm volatile("cp.async.cg.shared.global [%0], [%1], 16;" :: "r"(dst), "l"(src));
}
#define CP_COMMIT() asm volatile("cp.async.commit_group;" ::: "memory")
#define CP_WAIT(n)  asm volatile("cp.async.wait_group %0;" :: "n"(n) : "memory")

__device__ __forceinline__ void ldsm_x4(uint32_t addr, uint32_t& r0, uint32_t& r1,
                                        uint32_t& r2, uint32_t& r3) {
    asm volatile("ldmatrix.sync.aligned.m8n8.x4.shared.b16 {%0,%1,%2,%3}, [%4];"
                 : "=r"(r0), "=r"(r1), "=r"(r2), "=r"(r3) : "r"(addr));
}
__device__ __forceinline__ void mma16816(float* c, const uint32_t* a, const uint32_t* b) {
    asm volatile("mma.sync.aligned.m16n8k16.row.col.f32.bf16.bf16.f32 "
                 "{%0,%1,%2,%3}, {%4,%5,%6,%7}, {%8,%9}, {%0,%1,%2,%3};"
                 : "+f"(c[0]), "+f"(c[1]), "+f"(c[2]), "+f"(c[3])
                 : "r"(a[0]), "r"(a[1]), "r"(a[2]), "r"(a[3]), "r"(b[0]), "r"(b[1]));
}

// smem layout (bytes): padded rows 136 bf16 = 272 B; tile = 128*272 = 34816
#define ROWB 272
#define TILEB 34816
#define SM_A_HI 0
#define SM_A_LO 34816
#define SM_BH0  69632
#define SM_BH1  104448
#define SM_BL   139264
#define SMEM_TOTAL 174080

// ---------------- structure kernels ----------------
__global__ void zero_kernel() {
    int i = blockIdx.x * blockDim.x + threadIdx.x;
    if (i < NN * RR) g_cnt[i] = 0;
    if (i < NN) g_ncnt[i] = 0;
    if (i < NG * HD) g_pool[i] = 0.0f;
    if (i < NG) g_pcnt[i] = 0.0f;
}
__global__ void count_kernel(const int* __restrict__ dst, const int* __restrict__ rel,
                             const int* __restrict__ batch) {
    int e = blockIdx.x * blockDim.x + threadIdx.x;
    if (e < EE) {
        int d = dst[e];
        atomicAdd(&g_cnt[d * RR + rel[e]], 1);
        atomicAdd(&g_ncnt[d], 1);
    }
    if (e < NN)
        asm volatile("red.global.add.f32 [%0], %1;" :: "l"(&g_pcnt[batch[e]]), "f"(1.0f) : "memory");
}
__global__ void scan_bsum_kernel() {
    __shared__ int s[256];
    int i = blockIdx.x * 256 + threadIdx.x;
    int t = threadIdx.x;
    s[t] = (i < NN) ? g_ncnt[i] : 0;
    __syncthreads();
    for (int st = 128; st > 0; st >>= 1) {
        if (t < st) s[t] += s[t + st];
        __syncthreads();
    }
    if (t == 0) g_bsum[blockIdx.x] = s[0];
}
__global__ void scan_base_kernel() {
    __shared__ int s[256];
    int t = threadIdx.x;
    int v = (t < NBLK) ? g_bsum[t] : 0;
    s[t] = v;
    __syncthreads();
    for (int st = 1; st < 256; st <<= 1) {
        int add = (t >= st) ? s[t - st] : 0;
        __syncthreads();
        s[t] += add;
        __syncthreads();
    }
    if (t < NBLK) g_bbase[t] = s[t] - v;
}
__global__ void scan_final_kernel() {
    __shared__ int s[256];
    int i = blockIdx.x * 256 + threadIdx.x;
    int t = threadIdx.x;
    int v = (i < NN) ? g_ncnt[i] : 0;
    s[t] = v;
    __syncthreads();
    for (int st = 1; st < 256; st <<= 1) {
        int add = (t >= st) ? s[t - st] : 0;
        __syncthreads();
        s[t] += add;
        __syncthreads();
    }
    if (i < NN) {
        int off = g_bbase[blockIdx.x] + s[t] - v;
        g_off[i] = off;
        g_cur[i] = off;
    }
}
__global__ void scatter_kernel(const int* __restrict__ src, const int* __restrict__ dst,
                               const int* __restrict__ rel) {
    int e = blockIdx.x * blockDim.x + threadIdx.x;
    if (e >= EE) return;
    int d = dst[e], r = rel[e];
    int c = g_cnt[d * RR + r];
    float coef = 1.0f / (float)max(c, 1);
    int pos = atomicAdd(&g_cur[d], 1);
    g_edges[pos] = make_int2(src[e] * 8 + r, __float_as_int(coef));
}

// pack weights: split fp32 -> bf16 hi/lo, layout [ct][n][k]
__global__ void pack_w_kernel(const float* __restrict__ W, const float* __restrict__ root) {
    int i = blockIdx.x * blockDim.x + threadIdx.x;
    if (i >= 9 * 128 * 128) return;
    int ct = i >> 14;
    int rem = i & 16383;
    int n = rem >> 7;
    int k = rem & 127;
    float v = (ct < 8) ? W[((size_t)ct * 128 + k) * 128 + n] : root[(size_t)k * 128 + n];
    __nv_bfloat16 h, l;
    split_bf(v, h, l);
    g_wh[i] = h;
    g_wl[i] = l;
}

// ---------------- mma.sync GEMM (R7/R11 config): A[M,128] @ Wcat[128,1152] ----------------
__global__ __launch_bounds__(256, 1)
void gemm_mma_kernel(const float* __restrict__ x_in, const float* __restrict__ bias, int layer,
                     int mt0, __nv_bfloat16* __restrict__ msg) {
    extern __shared__ char smem[];
    const float* __restrict__ A = (layer == 0) ? x_in : g_hacc0;
    float* __restrict__ outroot = (layer == 0) ? g_hacc0 : g_hacc1;
    const bool relu = (layer != 0);

    const int tid = threadIdx.x;
    const int wid = tid >> 5, lane = tid & 31;
    const int warp_m = wid >> 2;
    const int warp_n = wid & 3;
    const int mt = blockIdx.x + mt0;
    const uint32_t su = smem_to_u32(smem);

    const uint32_t a_lane = (uint32_t)(warp_m * 64 + ((lane >> 3) & 1) * 8 + (lane & 7)) * ROWB
                          + (uint32_t)(lane >> 4) * 16;
    const uint32_t b_lane = (uint32_t)(warp_n * 32 + ((lane >> 4) & 1) * 8 + (lane & 7)) * ROWB
                          + (uint32_t)((lane >> 3) & 1) * 16;

    float2 bv[4];
    #pragma unroll
    for (int ni = 0; ni < 4; ni++)
        bv[ni] = *(const float2*)(bias + warp_n * 32 + ni * 8 + (lane & 3) * 2);

    // ---- load + split A tile (once per block) ----
    {
        int row = tid >> 1;
        int kh = (tid & 1) * 64;
        int m = mt * 128 + row;
        const float* ap = A + (size_t)m * 128 + kh;
        char* dh = smem + SM_A_HI + row * ROWB + kh * 2;
        char* dl = smem + SM_A_LO + row * ROWB + kh * 2;
        #pragma unroll
        for (int j = 0; j < 16; j++) {
            float4 v = make_float4(0.f, 0.f, 0.f, 0.f);
            if (m < NN) v = *(const float4*)(ap + 4 * j);
            if (relu) {
                v.x = fmaxf(v.x, 0.f); v.y = fmaxf(v.y, 0.f);
                v.z = fmaxf(v.z, 0.f); v.w = fmaxf(v.w, 0.f);
            }
            __nv_bfloat16 h0, l0, h1, l1, h2, l2, h3, l3;
            split_bf(v.x, h0, l0); split_bf(v.y, h1, l1);
            split_bf(v.z, h2, l2); split_bf(v.w, h3, l3);
            *(uint32_t*)(dh + 8 * j)     = pack_bf2(h0, h1);
            *(uint32_t*)(dh + 8 * j + 4) = pack_bf2(h2, h3);
            *(uint32_t*)(dl + 8 * j)     = pack_bf2(l0, l1);
            *(uint32_t*)(dl + 8 * j + 4) = pack_bf2(l2, l3);
        }
    }

    #define PF_TILE(gsrc, ct_, smoff) do {                                            \
        int n_ = tid >> 1, half_ = tid & 1;                                           \
        const char* s_ = (const char*)((gsrc) + (size_t)(ct_) * 16384 + n_ * 128 + half_ * 64); \
        uint32_t d_ = su + (smoff) + n_ * ROWB + half_ * 128;                         \
        _Pragma("unroll")                                                             \
        for (int j_ = 0; j_ < 8; j_++) cp16(d_ + 16 * j_, s_ + 16 * j_);              \
    } while (0)

    PF_TILE(g_wh, 0, SM_BH0);
    CP_COMMIT();

    const uint32_t as_h = su + SM_A_HI + a_lane;
    const uint32_t as_l = su + SM_A_LO + a_lane;
    const uint32_t bs_l = su + SM_BL + b_lane;

    #define LOAD_A4(dst, base, koff) do {                                             \
        _Pragma("unroll")                                                             \
        for (int mi = 0; mi < 4; mi++)                                                \
            ldsm_x4((base) + mi * (16 * ROWB) + (koff),                               \
                    dst[mi][0], dst[mi][1], dst[mi][2], dst[mi][3]);                  \
    } while (0)
    #define LOAD_B4(dst, base, koff) do {                                             \
        _Pragma("unroll")                                                             \
        for (int p = 0; p < 2; p++) {                                                 \
            uint32_t r0, r1, r2, r3;                                                  \
            ldsm_x4((base) + p * (16 * ROWB) + (koff), r0, r1, r2, r3);               \
            dst[2 * p][0] = r0; dst[2 * p][1] = r1;                                   \
            dst[2 * p + 1][0] = r2; dst[2 * p + 1][1] = r3;                           \
        }                                                                             \
    } while (0)

    for (int ct = 0; ct < 9; ct++) {
        const uint32_t bs_h = su + ((ct & 1) ? SM_BH1 : SM_BH0) + b_lane;

        if (ct < 8) {
            PF_TILE(g_wh, ct + 1, (ct & 1) ? SM_BH0 : SM_BH1);
            if (ct == 7) PF_TILE(g_wl, 8, SM_BL);
            CP_COMMIT();
            CP_WAIT(1);
        } else {
            CP_WAIT(0);
        }
        __syncthreads();

        float c[4][4][4];
        #pragma unroll
        for (int mi = 0; mi < 4; mi++)
            #pragma unroll
            for (int ni = 0; ni < 4; ni++)
                #pragma unroll
                for (int q = 0; q < 4; q++) c[mi][ni][q] = 0.0f;

        if (ct < 8) {
            uint32_t ah[2][4][4], bh[2][4][2];
            LOAD_A4(ah[0], as_h, 0u);
            LOAD_B4(bh[0], bs_h, 0u);
            #pragma unroll
            for (int k0 = 0; k0 < 8; k0++) {
                const int cur = k0 & 1;
                if (k0 < 7) {
                    LOAD_A4(ah[cur ^ 1], as_h, (uint32_t)(k0 + 1) * 32u);
                    LOAD_B4(bh[cur ^ 1], bs_h, (uint32_t)(k0 + 1) * 32u);
                }
                #pragma unroll
                for (int mi = 0; mi < 4; mi++)
                    #pragma unroll
                    for (int ni = 0; ni < 4; ni++)
                        mma16816(c[mi][ni], ah[cur][mi], bh[cur][ni]);
            }
            #pragma unroll
            for (int mi = 0; mi < 4; mi++) {
                int row0 = mt * 128 + warp_m * 64 + mi * 16 + (lane >> 2);
                int row1 = row0 + 8;
                #pragma unroll
                for (int ni = 0; ni < 4; ni++) {
                    int col = warp_n * 32 + ni * 8 + (lane & 3) * 2;
                    if (row0 < NN)
                        *(uint32_t*)(msg + (size_t)row0 * 1024 + ct * 128 + col) =
                            pack_bf2(__float2bfloat16(c[mi][ni][0]), __float2bfloat16(c[mi][ni][1]));
                    if (row1 < NN)
                        *(uint32_t*)(msg + (size_t)row1 * 1024 + ct * 128 + col) =
                            pack_bf2(__float2bfloat16(c[mi][ni][2]), __float2bfloat16(c[mi][ni][3]));
                }
            }
        } else {
            uint32_t ah[2][4][4], al[2][4][4], bh[2][4][2], bl[2][4][2];
            LOAD_A4(ah[0], as_h, 0u); LOAD_A4(al[0], as_l, 0u);
            LOAD_B4(bh[0], bs_h, 0u); LOAD_B4(bl[0], bs_l, 0u);
            #pragma unroll
            for (int k0 = 0; k0 < 8; k0++) {
                const int cur = k0 & 1;
                if (k0 < 7) {
                    const uint32_t koff = (uint32_t)(k0 + 1) * 32u;
                    LOAD_A4(ah[cur ^ 1], as_h, koff); LOAD_A4(al[cur ^ 1], as_l, koff);
                    LOAD_B4(bh[cur ^ 1], bs_h, koff); LOAD_B4(bl[cur ^ 1], bs_l, koff);
                }
                #pragma unroll
                for (int mi = 0; mi < 4; mi++)
                    #pragma unroll
                    for (int ni = 0; ni < 4; ni++) {
                        mma16816(c[mi][ni], ah[cur][mi], bh[cur][ni]);
                        mma16816(c[mi][ni], ah[cur][mi], bl[cur][ni]);
                        mma16816(c[mi][ni], al[cur][mi], bh[cur][ni]);
                    }
            }
            #pragma unroll
            for (int mi = 0; mi < 4; mi++) {
                int row0 = mt * 128 + warp_m * 64 + mi * 16 + (lane >> 2);
                int row1 = row0 + 8;
                #pragma unroll
                for (int ni = 0; ni < 4; ni++) {
                    int col = warp_n * 32 + ni * 8 + (lane & 3) * 2;
                    if (row0 < NN)
                        *(float2*)(outroot + (size_t)row0 * 128 + col) =
                            make_float2(c[mi][ni][0] + bv[ni].x, c[mi][ni][1] + bv[ni].y);
                    if (row1 < NN)
                        *(float2*)(outroot + (size_t)row1 * 128 + col) =
                            make_float2(c[mi][ni][2] + bv[ni].x, c[mi][ni][3] + bv[ni].y);
                }
            }
        }

        __syncthreads();
    }
    #undef LOAD_A4
    #undef LOAD_B4
    #undef PF_TILE
}

// ---------------- aggregation: one warp per dst node, no atomics, MLP 2 ----------------
__global__ void agg_kernel(const int* __restrict__ batch, int layer, int node0, int nnodes,
                           const __nv_bfloat16* __restrict__ msg) {
    int idx = (blockIdx.x * blockDim.x + threadIdx.x) >> 5;
    int lane = threadIdx.x & 31;
    if (idx >= nnodes) return;
    int node = node0 + idx;
    int off = g_off[node];
    int n = g_ncnt[node];

    float ax = 0.f, ay = 0.f, az = 0.f, aw = 0.f;
    int i = 0;
    for (; i + 1 < n; i += 2) {
        int2 e0 = __ldg(&g_edges[off + i]);
        int2 e1 = __ldg(&g_edges[off + i + 1]);
        const uint2 r0 = *(const uint2*)(msg + (size_t)e0.x * 128 + lane * 4);
        const uint2 r1 = *(const uint2*)(msg + (size_t)e1.x * 128 + lane * 4);
        float c0 = __int_as_float(e0.y);
        float c1 = __int_as_float(e1.y);
        float2 p0 = __bfloat1622float2(*reinterpret_cast<const __nv_bfloat162*>(&r0.x));
        float2 p1 = __bfloat1622float2(*reinterpret_cast<const __nv_bfloat162*>(&r0.y));
        float2 q0 = __bfloat1622float2(*reinterpret_cast<const __nv_bfloat162*>(&r1.x));
        float2 q1 = __bfloat1622float2(*reinterpret_cast<const __nv_bfloat162*>(&r1.y));
        ax = fmaf(p0.x, c0, ax); ay = fmaf(p0.y, c0, ay);
        az = fmaf(p1.x, c0, az); aw = fmaf(p1.y, c0, aw);
        ax = fmaf(q0.x, c1, ax); ay = fmaf(q0.y, c1, ay);
        az = fmaf(q1.x, c1, az); aw = fmaf(q1.y, c1, aw);
    }
    if (i < n) {
        int2 e0 = __ldg(&g_edges[off + i]);
        const uint2 r0 = *(const uint2*)(msg + (size_t)e0.x * 128 + lane * 4);
        float c0 = __int_as_float(e0.y);
        float2 p0 = __bfloat1622float2(*reinterpret_cast<const __nv_bfloat162*>(&r0.x));
        float2 p1 = __bfloat1622float2(*reinterpret_cast<const __nv_bfloat162*>(&r0.y));
        ax = fmaf(p0.x, c0, ax); ay = fmaf(p0.y, c0, ay);
        az = fmaf(p1.x, c0, az); aw = fmaf(p1.y, c0, aw);
    }

    if (layer == 0) {
        float4 h = *(float4*)(g_hacc0 + (size_t)node * 128 + lane * 4);
        h.x += ax; h.y += ay; h.z += az; h.w += aw;
        *(float4*)(g_hacc0 + (size_t)node * 128 + lane * 4) = h;
    } else {
        float4 h = *(float4*)(g_hacc1 + (size_t)node * 128 + lane * 4);
        h.x = fmaxf(h.x + ax, 0.f);
        h.y = fmaxf(h.y + ay, 0.f);
        h.z = fmaxf(h.z + az, 0.f);
        h.w = fmaxf(h.w + aw, 0.f);
        int g = __ldg(&batch[node]);
        float* o = g_pool + (size_t)g * HD + lane * 4;
        asm volatile("red.global.add.v4.f32 [%0], {%1, %2, %3, %4};"
                     :: "l"(o), "f"(h.x), "f"(h.y), "f"(h.z), "f"(h.w) : "memory");
    }
}

// ---------------- head ----------------
__global__ void final_kernel(const float* __restrict__ linW, const float* __restrict__ linb,
                             float* __restrict__ out) {
    int g = blockIdx.x;
    int tid = threadIdx.x;  // 128
    __shared__ float p[HD];
    float cnt = fmaxf(g_pcnt[g], 1.0f);
    p[tid] = g_pool[g * HD + tid] / cnt;
    __syncthreads();
    if (tid < NC) {
        float s = linb[tid];
        #pragma unroll 8
        for (int h = 0; h < HD; h++) s = fmaf(p[h], linW[h * NC + tid], s);
        out[g * NC + tid] = s;
    }
}

// ---------------- launch: fork-join overlap + wave-aligned layer-boundary pipeline ----------------
extern "C" void kernel_launch(void* const* d_in, const int* in_sizes, int n_in,
                              void* d_out, int out_size) {
    const float* x     = (const float*)d_in[0];
    const int*   eidx  = (const int*)d_in[1];
    const int*   etype = (const int*)d_in[2];
    const int*   batch = (const int*)d_in[3];
    const float* W1    = (const float*)d_in[4];
    const float* root1 = (const float*)d_in[5];
    const float* b1    = (const float*)d_in[6];
    const float* W2    = (const float*)d_in[7];
    const float* root2 = (const float*)d_in[8];
    const float* b2    = (const float*)d_in[9];
    const float* linW  = (const float*)d_in[10];
    const float* linb  = (const float*)d_in[11];
    float* out = (float*)d_out;

    const int* src = eidx;
    const int* dst = eidx + EE;

    static bool init_done = false;
    static cudaStream_t s2;
    static cudaEvent_t ev_fork, ev_struct, ev_g0, ev_a0a, ev_a0b, ev_g1;
    static __nv_bfloat16 *p_xwb0, *p_xwb1;
    if (!init_done) {
        cudaFuncSetAttribute(gemm_mma_kernel, cudaFuncAttributeMaxDynamicSharedMemorySize, SMEM_TOTAL);
        cudaStreamCreateWithFlags(&s2, cudaStreamNonBlocking);
        cudaEventCreateWithFlags(&ev_fork, cudaEventDisableTiming);
        cudaEventCreateWithFlags(&ev_struct, cudaEventDisableTiming);
        cudaEventCreateWithFlags(&ev_g0, cudaEventDisableTiming);
        cudaEventCreateWithFlags(&ev_a0a, cudaEventDisableTiming);
        cudaEventCreateWithFlags(&ev_a0b, cudaEventDisableTiming);
        cudaEventCreateWithFlags(&ev_g1, cudaEventDisableTiming);
        cudaGetSymbolAddress((void**)&p_xwb0, g_xwb0);
        cudaGetSymbolAddress((void**)&p_xwb1, g_xwb1);
        init_done = true;
    }

    int pack_blocks = (9 * 128 * 128 + 255) / 256;
    const int aggA_blocks = (CH_NODES0 * 32 + 255) / 256;
    const int aggB_blocks = ((NN - CH_NODES0) * 32 + 255) / 256;
    const int agg_blocks  = (NN * 32 + 255) / 256;

    // fork stream B off the main (capture) stream
    cudaEventRecord(ev_fork, 0);
    cudaStreamWaitEvent(s2, ev_fork, 0);

    // ---- stream B: structure phase (independent of weights/GEMM) ----
    zero_kernel<<<(NN * RR + 255) / 256, 256, 0, s2>>>();
    count_kernel<<<(EE + 255) / 256, 256, 0, s2>>>(dst, etype, batch);
    scan_bsum_kernel<<<NBLK, 256, 0, s2>>>();
    scan_base_kernel<<<1, 256, 0, s2>>>();
    scan_final_kernel<<<NBLK, 256, 0, s2>>>();
    scatter_kernel<<<(EE + 255) / 256, 256, 0, s2>>>(src, dst, etype);
    cudaEventRecord(ev_struct, s2);

    // ---- main: pack W1 + full layer-1 GEMM (messages -> buf0) ----
    pack_w_kernel<<<pack_blocks, 256>>>(W1, root1);
    gemm_mma_kernel<<<NTILES, 256, SMEM_TOTAL>>>(x, b1, 0, 0, p_xwb0);
    cudaEventRecord(ev_g0, 0);

    // stream B: pack W2 once gemm(0) stops reading the weight buffers
    cudaStreamWaitEvent(s2, ev_g0, 0);
    pack_w_kernel<<<pack_blocks, 256, 0, s2>>>(W2, root2);

    // ---- main: agg(0) in two node chunks (reads buf0, writes hacc0) ----
    cudaStreamWaitEvent(0, ev_struct, 0);
    agg_kernel<<<aggA_blocks, 256>>>(batch, 0, 0, CH_NODES0, p_xwb0);
    cudaEventRecord(ev_a0a, 0);
    agg_kernel<<<aggB_blocks, 256>>>(batch, 0, CH_NODES0, NN - CH_NODES0, p_xwb0);
    cudaEventRecord(ev_a0b, 0);

    // ---- stream B: layer-2 GEMM, wave-aligned chunks (writes buf1) ----
    // chunk A = exactly one full wave (148 CTAs); overlaps agg(0) chunk B
    cudaStreamWaitEvent(s2, ev_a0a, 0);
    gemm_mma_kernel<<<CH_TILES0, 256, SMEM_TOTAL, s2>>>(x, b2, 1, 0, p_xwb1);
    cudaStreamWaitEvent(s2, ev_a0b, 0);
    gemm_mma_kernel<<<CH_TILES1, 256, SMEM_TOTAL, s2>>>(x, b2, 1, CH_TILES0, p_xwb1);
    cudaEventRecord(ev_g1, s2);

    // ---- main: agg(1) (needs all of buf1) + head ----
    cudaStreamWaitEvent(0, ev_g1, 0);
    agg_kernel<<<agg_blocks, 256>>>(batch, 1, 0, NN, p_xwb1);
    final_kernel<<<NG, 128>>>(linW, linb, out);
}